// round 13
// baseline (speedup 1.0000x reference)
#include <cuda_runtime.h>
#include <math.h>

typedef unsigned long long u64;

#define B_    128
#define T_    256
#define NC    128
#define WD    512
#define UNITS 512
#define ZCOLS 2048   // 4*UNITS, Keras gate order: i | f | g | o (512 cols each)

// ---------------- device-global scratch (alloc-free) ----------------
__device__ float g_z0[(size_t)T_ * B_ * ZCOLS]; // [t*128+b][2048] = x@W + b
__device__ float g_h[2][UNITS * B_];            // ping-pong h, layout [unit][batch]
__device__ float g_c[B_ * UNITS];               // c state, layout [batch][unit]
__device__ float g_wsum[ZCOLS];                 // 1e-5 * colsum of one-hot W rows
__device__ float g_plog[16][B_][NC];            // partial logits per 32-unit slice
__device__ int   g_idx[B_];                     // argmax feedback

__device__ __forceinline__ float sigf(float x) { return 1.f / (1.f + expf(-x)); }

// ---------------- packed f32x2 helpers (bit-exact fp32, 2 FMA/instr) ---------
__device__ __forceinline__ u64 fma2(u64 a, u64 b, u64 c) {
    u64 d; asm("fma.rn.f32x2 %0, %1, %2, %3;" : "=l"(d) : "l"(a), "l"(b), "l"(c));
    return d;
}
__device__ __forceinline__ float2 unpack2(u64 v) {
    float lo, hi; asm("mov.b64 {%0,%1}, %2;" : "=f"(lo), "=f"(hi) : "l"(v));
    return make_float2(lo, hi);
}

// ---------------- zero h0, c0 ----------------
__global__ void k_init() {
    int i = blockIdx.x * 256 + threadIdx.x;   // 256 blocks * 256 = 65536
    g_h[0][i] = 0.f;
    g_c[i]    = 0.f;
    if (i < B_) g_idx[i] = 0;
}

// ---------------- start-word vector: word0 = 1e-5 everywhere ----------------
__global__ void k_wsum(const float* __restrict__ W) {
    int col = blockIdx.x * 256 + threadIdx.x; // 2048
    float s = 0.f;
    for (int cc = 0; cc < NC; cc++)
        s += W[(size_t)(NC + WD + cc) * ZCOLS + col];
    g_wsum[col] = 1e-5f * s;
}

// ---------------- hoisted GEMM: z0[row=t*128+b][col] = x_row @ W[0:640] + b ----
// 64x64 tile, 256 threads, 4 rows x 4 cols per thread, f32x2 (cols packed,
// x duplicated in smem as float2(v,v)).
__global__ void __launch_bounds__(256) k_z0(
    const float* __restrict__ xc, const float* __restrict__ xw,
    const float* __restrict__ W,  const float* __restrict__ bias)
{
    const int col0 = blockIdx.x * 64;     // 32 blocks
    const int row0 = blockIdx.y * 64;     // 512 blocks
    const int tid = threadIdx.x;
    const int tc = tid & 15;              // col group (4 cols = 2 packed pairs)
    const int tr = tid >> 4;              // row group (4 rows)

    __shared__ __align__(16) float2 sx2[64][34];  // [row][k], duplicated (v,v)
    __shared__ __align__(16) float  sw[32][68];   // [k][col], 272B rows

    u64 az0[4], az1[4];   // [row r]: col pair (4tc,4tc+1) / (4tc+2,4tc+3)
    #pragma unroll
    for (int r = 0; r < 4; r++) { az0[r] = 0ull; az1[r] = 0ull; }

    for (int k0 = 0; k0 < NC + WD; k0 += 32) {
        const bool isChar = (k0 < NC);    // chunks never straddle (128 % 32 == 0)
        #pragma unroll
        for (int r = 0; r < 8; r++) {
            int idx = tid + r * 256;
            int rr = idx >> 5, kk = idx & 31;
            int row = row0 + rr;
            int tt = row >> 7, bb = row & 127;   // row = t*128 + b
            float v = isChar ? xc[((size_t)bb * T_ + tt) * NC + (k0 + kk)]
                             : xw[((size_t)bb * T_ + tt) * WD + (k0 - NC + kk)];
            sx2[rr][kk] = make_float2(v, v);
        }
        #pragma unroll
        for (int r = 0; r < 8; r++) {
            int idx = tid + r * 256;
            int kk = idx >> 6, cc = idx & 63;
            sw[kk][cc] = W[(size_t)(k0 + kk) * ZCOLS + col0 + cc];
        }
        __syncthreads();
        #pragma unroll
        for (int kk = 0; kk < 32; kk++) {
            ulonglong2 wq = *(const ulonglong2*)&sw[kk][4 * tc];  // 16B-aligned
            #pragma unroll
            for (int r = 0; r < 4; r++) {
                u64 xd = *(const u64*)&sx2[4 * tr + r][kk];       // (x,x)
                az0[r] = fma2(wq.x, xd, az0[r]);
                az1[r] = fma2(wq.y, xd, az1[r]);
            }
        }
        __syncthreads();
    }

    const float4 bq = *(const float4*)&bias[col0 + 4 * tc];
    #pragma unroll
    for (int r = 0; r < 4; r++) {
        int row = row0 + 4 * tr + r;
        float2 v0 = unpack2(az0[r]);
        float2 v1 = unpack2(az1[r]);
        float4 o;
        o.x = v0.x + bq.x;
        o.y = v0.y + bq.y;
        o.z = v1.x + bq.z;
        o.w = v1.y + bq.w;
        *(float4*)(g_z0 + ((size_t)row << 11) + col0 + 4 * tc) = o;
    }
}

// ---------------- k_step staging helpers (double-buffered) ----------------
__device__ __forceinline__ void ldg_chunk(
    const float* __restrict__ U, const float* __restrict__ h_in,
    int k0, int j0, int b0, int tid, float4 pu[8], float ph[4])
{
    #pragma unroll
    for (int r = 0; r < 8; r++) {
        int idx = tid + r * 128;
        int kk = idx >> 5, c4 = idx & 31;   // c4: float4 index within 128-col row
        pu[r] = *(const float4*)&U[(size_t)(k0 + kk) * ZCOLS
                                   + (c4 >> 3) * UNITS + j0 + (c4 & 7) * 4];
    }
    #pragma unroll
    for (int r = 0; r < 4; r++) {
        int idx = tid + r * 128;
        int kk = idx >> 4, bb = idx & 15;
        ph[r] = h_in[(k0 + kk) * B_ + b0 + bb];
    }
}
__device__ __forceinline__ void sts_chunk(
    float su[32][128], float2 sh2[32][16],
    int tid, const float4 pu[8], const float ph[4])
{
    #pragma unroll
    for (int r = 0; r < 8; r++) {
        int idx = tid + r * 128;
        int kk = idx >> 5, c4 = idx & 31;
        *(float4*)&su[kk][c4 * 4] = pu[r];
    }
    #pragma unroll
    for (int r = 0; r < 4; r++) {
        int idx = tid + r * 128;
        int kk = idx >> 4, bb = idx & 15;
        sh2[kk][bb] = make_float2(ph[r], ph[r]);
    }
}

// ---------------- per-step fused: h@U, z assembly, LSTM cell, partial logits --
// grid (16 unit-tiles, 8 batch-tiles), 128 threads.
// GEMM: thread = (cg: 4 su-cols as 2 packed pairs, bg: 4 batches), f32x2.
__global__ void __launch_bounds__(128) k_step(
    const float* __restrict__ W, const float* __restrict__ U,
    const float* __restrict__ Ws, int t)
{
    const int jt = blockIdx.x;            // units j0..j0+31
    const int bt = blockIdx.y;            // batches b0..b0+15
    const int j0 = jt * 32, b0 = bt * 16;
    const int tid = threadIdx.x;
    const int cg = tid & 31;              // su cols 4cg..4cg+3
    const int bg = tid >> 5;              // batches 4bg..4bg+3

    const float* __restrict__ h_in  = g_h[t & 1];
    float* __restrict__       h_out = g_h[(t & 1) ^ 1];

    __shared__ __align__(16) float  su[2][32][128];  // [buf][k][gate*32+jl]
    __shared__ __align__(16) float2 sh2[2][32][16];  // [buf][k][b], (v,v)
    __shared__ __align__(16) float  sz[16][132];     // [b][col]
    __shared__ __align__(16) float  shv[16][36];     // [b][jl]

    u64 a0[4], a1[4];   // [bi]: col pair (4cg,4cg+1) / (4cg+2,4cg+3)
    #pragma unroll
    for (int i = 0; i < 4; i++) { a0[i] = 0ull; a1[i] = 0ull; }

    float4 pu[8];
    float  ph[4];

    ldg_chunk(U, h_in, 0, j0, b0, tid, pu, ph);
    sts_chunk(su[0], sh2[0], tid, pu, ph);
    __syncthreads();

    int cur = 0;
    for (int ch = 0; ch < 16; ch++) {
        if (ch < 15) ldg_chunk(U, h_in, (ch + 1) * 32, j0, b0, tid, pu, ph);
        #pragma unroll
        for (int kk = 0; kk < 32; kk++) {
            ulonglong2 uq = *(const ulonglong2*)&su[cur][kk][4 * cg];
            #pragma unroll
            for (int bi = 0; bi < 4; bi++) {
                u64 hd = *(const u64*)&sh2[cur][kk][4 * bg + bi];  // (h,h)
                a0[bi] = fma2(uq.x, hd, a0[bi]);
                a1[bi] = fma2(uq.y, hd, a1[bi]);
            }
        }
        if (ch < 15) {
            sts_chunk(su[cur ^ 1], sh2[cur ^ 1], tid, pu, ph);
            __syncthreads();
            cur ^= 1;
        }
    }

    // unpack packed accumulators to scalar [ci][bi] (ci = col offset 0..3)
    float accs[4][4];
    #pragma unroll
    for (int bi = 0; bi < 4; bi++) {
        float2 v0 = unpack2(a0[bi]);
        float2 v1 = unpack2(a1[bi]);
        accs[0][bi] = v0.x; accs[1][bi] = v0.y;
        accs[2][bi] = v1.x; accs[3][bi] = v1.y;
    }

    // z assembly: z = h@U + z0 + word_vec@W, into sz[b][col]
    {
        const int g = cg >> 3;                               // gate of this col quad
        const int zcolb = g * UNITS + j0 + ((4 * cg) & 31);  // global z column base
        #pragma unroll
        for (int bi = 0; bi < 4; bi++) {
            int b = b0 + 4 * bg + bi;
            const float* z0r = g_z0 + ((size_t)(t * B_ + b) << 11) + zcolb;
            float e0, e1, e2, e3;
            if (t == 0) {
                const float* wsr = g_wsum + zcolb;
                e0 = wsr[0]; e1 = wsr[1]; e2 = wsr[2]; e3 = wsr[3];
            } else {
                const float* wr = W + (size_t)(NC + WD + g_idx[b]) * ZCOLS + zcolb;
                e0 = wr[0]; e1 = wr[1]; e2 = wr[2]; e3 = wr[3];
            }
            float4 zq;
            zq.x = accs[0][bi] + z0r[0] + e0;
            zq.y = accs[1][bi] + z0r[1] + e1;
            zq.z = accs[2][bi] + z0r[2] + e2;
            zq.w = accs[3][bi] + z0r[3] + e3;
            *(float4*)&sz[4 * bg + bi][4 * cg] = zq;         // 16B-aligned
        }
    }
    __syncthreads();

    // LSTM cell: thread = (jl, bq), 4 batches each
    {
        const int jl = tid & 31, bq = tid >> 5;
        #pragma unroll
        for (int bi = 0; bi < 4; bi++) {
            int bb = 4 * bq + bi, b = b0 + bb;
            float zi = sz[bb][jl];
            float zf = sz[bb][32 + jl];
            float zg = sz[bb][64 + jl];
            float zo = sz[bb][96 + jl];
            float ig = sigf(zi), fg = sigf(zf);
            float gg = tanhf(zg), og = sigf(zo);
            int ci = b * UNITS + (j0 + jl);
            float cn = fg * g_c[ci] + ig * gg;
            g_c[ci] = cn;
            float hv = og * tanhf(cn);
            h_out[(j0 + jl) * B_ + b] = hv;
            shv[bb][jl] = hv;
        }
    }
    __syncthreads();

    // partial logits: plog[jt][b][c] = sum_jj hv[b][jj] * Ws[j0+jj][c]
    {
        const int c = tid;   // 0..127
        float wv[32];
        #pragma unroll
        for (int jj = 0; jj < 32; jj++) wv[jj] = Ws[(j0 + jj) * NC + c];
        #pragma unroll
        for (int q = 0; q < 16; q++) {
            float ps = 0.f;
            #pragma unroll
            for (int jj = 0; jj < 32; jj++) ps += shv[q][jj] * wv[jj];
            g_plog[jt][b0 + q][c] = ps;
        }
    }
}

// ---------------- reduce + argmax (first-index ties), FLOAT32 output ---------
__global__ void k_argmax(const float* __restrict__ bs, float* __restrict__ out, int t) {
    const int b = blockIdx.x;      // 128
    const int c = threadIdx.x;     // 128
    float s = bs[c];
    #pragma unroll
    for (int q = 0; q < 16; q++) s += g_plog[q][b][c];

    __shared__ float sv[128];
    __shared__ int   si[128];
    sv[c] = s; si[c] = c;
    __syncthreads();
    #pragma unroll
    for (int off = 64; off > 0; off >>= 1) {
        if (c < off) {
            float ov = sv[c + off]; int oi = si[c + off];
            if (ov > sv[c] || (ov == sv[c] && oi < si[c])) { sv[c] = ov; si[c] = oi; }
        }
        __syncthreads();
    }
    if (c == 0) {
        g_idx[b] = si[0];
        out[b * T_ + t] = (float)si[0];   // float32 output
    }
}

// ---------------- launch: bind by element count, positional fallback ---------
extern "C" void kernel_launch(void* const* d_in, const int* in_sizes, int n_in,
                              void* d_out, int out_size) {
    const float *xc = 0, *xw = 0, *W = 0, *U = 0, *bb = 0, *Ws = 0, *bs = 0;
    for (int i = 0; i < n_in; i++) {
        switch (in_sizes[i]) {
            case 4194304:  xc = (const float*)d_in[i]; break; // 128*256*128
            case 16777216: xw = (const float*)d_in[i]; break; // 128*256*512
            case 1572864:  W  = (const float*)d_in[i]; break; // 768*2048
            case 1048576:  U  = (const float*)d_in[i]; break; // 512*2048
            case 2048:     bb = (const float*)d_in[i]; break;
            case 65536:    Ws = (const float*)d_in[i]; break; // 512*128
            case 128:      bs = (const float*)d_in[i]; break;
            default: break;
        }
    }
    if (!xc || !xw || !W || !U || !bb || !Ws || !bs) {
        xc = (const float*)d_in[0];
        xw = (const float*)d_in[1];
        W  = (const float*)d_in[2];
        U  = (const float*)d_in[3];
        bb = (const float*)d_in[4];
        Ws = (const float*)d_in[5];
        bs = (const float*)d_in[6];
    }
    float* out = (float*)d_out;   // [128, 256] float32

    k_init<<<256, 256>>>();
    k_wsum<<<8, 256>>>(W);
    k_z0<<<dim3(32, 512), 256>>>(xc, xw, W, bb);

    for (int t = 0; t < T_; t++) {
        k_step<<<dim3(16, 8), 128>>>(W, U, Ws, t);
        k_argmax<<<128, 128>>>(bs, out, t);
    }
}

// round 15
// speedup vs baseline: 1.2529x; 1.2529x over previous
#include <cuda_runtime.h>
#include <math.h>

typedef unsigned long long u64;

#define B_    128
#define T_    256
#define NC    128
#define WD    512
#define UNITS 512
#define ZCOLS 2048   // 4*UNITS, Keras gate order: i | f | g | o (512 cols each)

// ---------------- device-global scratch (alloc-free) ----------------
__device__ float g_z0[(size_t)T_ * B_ * ZCOLS]; // [t*128+b][2048] = x@W + b
__device__ float g_h[2][UNITS * B_];            // ping-pong h, layout [unit][batch]
__device__ float g_c[B_ * UNITS];               // c state, layout [batch][unit]
__device__ float g_wsum[ZCOLS];                 // 1e-5 * colsum of one-hot W rows
__device__ float g_plog[16][B_][NC];            // partial logits per 32-unit slice
__device__ int   g_idx[B_];                     // argmax feedback

__device__ __forceinline__ float sigf(float x) { return 1.f / (1.f + expf(-x)); }

// ---------------- packed f32x2 helpers (bit-exact fp32, 2 FMA/instr) ---------
__device__ __forceinline__ u64 fma2(u64 a, u64 b, u64 c) {
    u64 d; asm("fma.rn.f32x2 %0, %1, %2, %3;" : "=l"(d) : "l"(a), "l"(b), "l"(c));
    return d;
}
__device__ __forceinline__ float2 unpack2(u64 v) {
    float lo, hi; asm("mov.b64 {%0,%1}, %2;" : "=f"(lo), "=f"(hi) : "l"(v));
    return make_float2(lo, hi);
}

// ---------------- zero h0, c0 ----------------
__global__ void k_init() {
    int i = blockIdx.x * 256 + threadIdx.x;   // 256 blocks * 256 = 65536
    g_h[0][i] = 0.f;
    g_c[i]    = 0.f;
    if (i < B_) g_idx[i] = 0;
}

// ---------------- start-word vector: word0 = 1e-5 everywhere ----------------
__global__ void k_wsum(const float* __restrict__ W) {
    int col = blockIdx.x * 256 + threadIdx.x; // 2048
    float s = 0.f;
    for (int cc = 0; cc < NC; cc++)
        s += W[(size_t)(NC + WD + cc) * ZCOLS + col];
    g_wsum[col] = 1e-5f * s;
}

// ---------------- hoisted GEMM: z0 = x @ W[0:640] + b  (ROUND-12 PROVEN) ----
// 64x64 tile, 256 threads, 4 rows x 4 cols per thread, scalar FFMA.
__global__ void __launch_bounds__(256) k_z0(
    const float* __restrict__ xc, const float* __restrict__ xw,
    const float* __restrict__ W,  const float* __restrict__ bias)
{
    const int col0 = blockIdx.x * 64;     // 32 blocks
    const int row0 = blockIdx.y * 64;     // 512 blocks
    const int tid = threadIdx.x;
    const int tc = tid & 15;              // col group (4 cols)
    const int tr = tid >> 4;              // row group (4 rows)

    __shared__ __align__(16) float sx[64][33];  // [row][k]
    __shared__ __align__(16) float sw[32][68];  // [k][col], 272B rows

    float acc[4][4];
    #pragma unroll
    for (int r = 0; r < 4; r++)
        #pragma unroll
        for (int c = 0; c < 4; c++) acc[r][c] = 0.f;

    for (int k0 = 0; k0 < NC + WD; k0 += 32) {
        const bool isChar = (k0 < NC);    // chunks never straddle (128 % 32 == 0)
        #pragma unroll
        for (int r = 0; r < 8; r++) {
            int idx = tid + r * 256;
            int rr = idx >> 5, kk = idx & 31;
            int row = row0 + rr;
            int tt = row >> 7, bb = row & 127;   // row = t*128 + b
            sx[rr][kk] = isChar ? xc[((size_t)bb * T_ + tt) * NC + (k0 + kk)]
                                : xw[((size_t)bb * T_ + tt) * WD + (k0 - NC + kk)];
        }
        #pragma unroll
        for (int r = 0; r < 8; r++) {
            int idx = tid + r * 256;
            int kk = idx >> 6, cc = idx & 63;
            sw[kk][cc] = W[(size_t)(k0 + kk) * ZCOLS + col0 + cc];
        }
        __syncthreads();
        #pragma unroll
        for (int kk = 0; kk < 32; kk++) {
            float4 wq = *(const float4*)&sw[kk][4 * tc];   // 16B-aligned
            #pragma unroll
            for (int r = 0; r < 4; r++) {
                float xv = sx[4 * tr + r][kk];
                acc[r][0] += xv * wq.x;
                acc[r][1] += xv * wq.y;
                acc[r][2] += xv * wq.z;
                acc[r][3] += xv * wq.w;
            }
        }
        __syncthreads();
    }

    const float4 bq = *(const float4*)&bias[col0 + 4 * tc];
    #pragma unroll
    for (int r = 0; r < 4; r++) {
        int row = row0 + 4 * tr + r;
        float4 o;
        o.x = acc[r][0] + bq.x;
        o.y = acc[r][1] + bq.y;
        o.z = acc[r][2] + bq.z;
        o.w = acc[r][3] + bq.w;
        *(float4*)(g_z0 + ((size_t)row << 11) + col0 + 4 * tc) = o;
    }
}

// ---------------- k_step staging helpers (256 threads, double-buffered) ------
__device__ __forceinline__ void ldg_chunk(
    const float* __restrict__ U, const float* __restrict__ h_in,
    int k0, int j0, int b0, int tid, float4 pu[4], float ph[2])
{
    #pragma unroll
    for (int r = 0; r < 4; r++) {
        int idx = tid + r * 256;            // [0,1024): 32 rows x 32 float4
        int kk = idx >> 5, c4 = idx & 31;
        pu[r] = *(const float4*)&U[(size_t)(k0 + kk) * ZCOLS
                                   + (c4 >> 3) * UNITS + j0 + (c4 & 7) * 4];
    }
    #pragma unroll
    for (int r = 0; r < 2; r++) {
        int idx = tid + r * 256;            // [0,512): 32 rows x 16 b
        int kk = idx >> 4, bb = idx & 15;
        ph[r] = h_in[(k0 + kk) * B_ + b0 + bb];
    }
}
__device__ __forceinline__ void sts_chunk(
    float su[32][128], float2 sh2[32][16],
    int tid, const float4 pu[4], const float ph[2])
{
    #pragma unroll
    for (int r = 0; r < 4; r++) {
        int idx = tid + r * 256;
        int kk = idx >> 5, c4 = idx & 31;
        *(float4*)&su[kk][c4 * 4] = pu[r];
    }
    #pragma unroll
    for (int r = 0; r < 2; r++) {
        int idx = tid + r * 256;
        int kk = idx >> 4, bb = idx & 15;
        sh2[kk][bb] = make_float2(ph[r], ph[r]);
    }
}

// ---------------- per-step fused: h@U (k-split), cell, partial logits --------
// grid (16 unit-tiles, 8 batch-tiles), 256 threads.
// Thread: cg = tid&31 (4 su-cols as 2 packed pairs), bg = (tid>>5)&3 (4 batches),
//         kw = tid>>7 (k-half: kk in [16kw,16kw+16) of each 32-row chunk).
__global__ void __launch_bounds__(256) k_step(
    const float* __restrict__ W, const float* __restrict__ U,
    const float* __restrict__ Ws, int t)
{
    const int jt = blockIdx.x;            // units j0..j0+31
    const int bt = blockIdx.y;            // batches b0..b0+15
    const int j0 = jt * 32, b0 = bt * 16;
    const int tid = threadIdx.x;
    const int cg = tid & 31;
    const int bg = (tid >> 5) & 3;
    const int kw = tid >> 7;              // 0 or 1

    const float* __restrict__ h_in  = g_h[t & 1];
    float* __restrict__       h_out = g_h[(t & 1) ^ 1];

    __shared__ __align__(16) float  su[2][32][128];  // [buf][k][gate*32+jl]
    __shared__ __align__(16) float2 sh2[2][32][16];  // [buf][k][b], (v,v)
    __shared__ __align__(16) float  sz[16][132];     // [b][col]
    __shared__ __align__(16) float  shv[16][36];     // [b][jl]
    __shared__ __align__(16) float  red[128][17];    // k-split reduction

    u64 a0[4], a1[4];   // [bi]: col pair (4cg,4cg+1) / (4cg+2,4cg+3)
    #pragma unroll
    for (int i = 0; i < 4; i++) { a0[i] = 0ull; a1[i] = 0ull; }

    float4 pu[4];
    float  ph[2];

    ldg_chunk(U, h_in, 0, j0, b0, tid, pu, ph);
    sts_chunk(su[0], sh2[0], tid, pu, ph);
    __syncthreads();

    int cur = 0;
    for (int ch = 0; ch < 16; ch++) {
        if (ch < 15) ldg_chunk(U, h_in, (ch + 1) * 32, j0, b0, tid, pu, ph);
        const int kbase = 16 * kw;
        #pragma unroll
        for (int kk = 0; kk < 16; kk++) {
            ulonglong2 uq = *(const ulonglong2*)&su[cur][kbase + kk][4 * cg];
            #pragma unroll
            for (int bi = 0; bi < 4; bi++) {
                u64 hd = *(const u64*)&sh2[cur][kbase + kk][4 * bg + bi]; // (h,h)
                a0[bi] = fma2(uq.x, hd, a0[bi]);
                a1[bi] = fma2(uq.y, hd, a1[bi]);
            }
        }
        if (ch < 15) {
            sts_chunk(su[cur ^ 1], sh2[cur ^ 1], tid, pu, ph);
            __syncthreads();
            cur ^= 1;
        }
    }

    // unpack packed accumulators to scalar [ci][bi]
    float accs[4][4];
    #pragma unroll
    for (int bi = 0; bi < 4; bi++) {
        float2 v0 = unpack2(a0[bi]);
        float2 v1 = unpack2(a1[bi]);
        accs[0][bi] = v0.x; accs[1][bi] = v0.y;
        accs[2][bi] = v1.x; accs[3][bi] = v1.y;
    }

    // fold upper k-half into lower (threads tid and tid+128 share (cg,bg))
    if (kw == 1) {
        #pragma unroll
        for (int ci = 0; ci < 4; ci++)
            #pragma unroll
            for (int bi = 0; bi < 4; bi++)
                red[tid - 128][ci * 4 + bi] = accs[ci][bi];
    }
    __syncthreads();
    if (kw == 0) {
        #pragma unroll
        for (int ci = 0; ci < 4; ci++)
            #pragma unroll
            for (int bi = 0; bi < 4; bi++)
                accs[ci][bi] += red[tid][ci * 4 + bi];

        // z assembly: z = h@U + z0 + word_vec@W, into sz[b][col]
        const int g = cg >> 3;                               // gate of this col quad
        const int zcolb = g * UNITS + j0 + ((4 * cg) & 31);  // global z column base
        #pragma unroll
        for (int bi = 0; bi < 4; bi++) {
            int b = b0 + 4 * bg + bi;
            const float* z0r = g_z0 + ((size_t)(t * B_ + b) << 11) + zcolb;
            float e0, e1, e2, e3;
            if (t == 0) {
                const float* wsr = g_wsum + zcolb;
                e0 = wsr[0]; e1 = wsr[1]; e2 = wsr[2]; e3 = wsr[3];
            } else {
                const float* wr = W + (size_t)(NC + WD + g_idx[b]) * ZCOLS + zcolb;
                e0 = wr[0]; e1 = wr[1]; e2 = wr[2]; e3 = wr[3];
            }
            float4 zq;
            zq.x = accs[0][bi] + z0r[0] + e0;
            zq.y = accs[1][bi] + z0r[1] + e1;
            zq.z = accs[2][bi] + z0r[2] + e2;
            zq.w = accs[3][bi] + z0r[3] + e3;
            *(float4*)&sz[4 * bg + bi][4 * cg] = zq;         // 16B-aligned
        }
    }
    __syncthreads();

    // LSTM cell: lower 128 threads, thread = (jl, bq), 4 batches each
    if (kw == 0) {
        const int jl = tid & 31, bq = tid >> 5;   // bq in 0..3
        #pragma unroll
        for (int bi = 0; bi < 4; bi++) {
            int bb = 4 * bq + bi, b = b0 + bb;
            float zi = sz[bb][jl];
            float zf = sz[bb][32 + jl];
            float zg = sz[bb][64 + jl];
            float zo = sz[bb][96 + jl];
            float ig = sigf(zi), fg = sigf(zf);
            float gg = tanhf(zg), og = sigf(zo);
            int ci = b * UNITS + (j0 + jl);
            float cn = fg * g_c[ci] + ig * gg;
            g_c[ci] = cn;
            float hv = og * tanhf(cn);
            h_out[(j0 + jl) * B_ + b] = hv;
            shv[bb][jl] = hv;
        }
    }
    __syncthreads();

    // partial logits: all 256 threads; thread (c = tid&127, qh = tid>>7) does 8 q
    {
        const int c = tid & 127;
        const int q0 = (tid >> 7) * 8;
        float wv[32];
        #pragma unroll
        for (int jj = 0; jj < 32; jj++) wv[jj] = Ws[(j0 + jj) * NC + c];
        #pragma unroll
        for (int qi = 0; qi < 8; qi++) {
            int q = q0 + qi;
            float ps = 0.f;
            #pragma unroll
            for (int jj = 0; jj < 32; jj++) ps += shv[q][jj] * wv[jj];
            g_plog[jt][b0 + q][c] = ps;
        }
    }
}

// ---------------- reduce + argmax (first-index ties), FLOAT32 output ---------
__global__ void k_argmax(const float* __restrict__ bs, float* __restrict__ out, int t) {
    const int b = blockIdx.x;      // 128
    const int c = threadIdx.x;     // 128
    float s = bs[c];
    #pragma unroll
    for (int q = 0; q < 16; q++) s += g_plog[q][b][c];

    __shared__ float sv[128];
    __shared__ int   si[128];
    sv[c] = s; si[c] = c;
    __syncthreads();
    #pragma unroll
    for (int off = 64; off > 0; off >>= 1) {
        if (c < off) {
            float ov = sv[c + off]; int oi = si[c + off];
            if (ov > sv[c] || (ov == sv[c] && oi < si[c])) { sv[c] = ov; si[c] = oi; }
        }
        __syncthreads();
    }
    if (c == 0) {
        g_idx[b] = si[0];
        out[b * T_ + t] = (float)si[0];   // float32 output
    }
}

// ---------------- launch: bind by element count, positional fallback ---------
extern "C" void kernel_launch(void* const* d_in, const int* in_sizes, int n_in,
                              void* d_out, int out_size) {
    const float *xc = 0, *xw = 0, *W = 0, *U = 0, *bb = 0, *Ws = 0, *bs = 0;
    for (int i = 0; i < n_in; i++) {
        switch (in_sizes[i]) {
            case 4194304:  xc = (const float*)d_in[i]; break; // 128*256*128
            case 16777216: xw = (const float*)d_in[i]; break; // 128*256*512
            case 1572864:  W  = (const float*)d_in[i]; break; // 768*2048
            case 1048576:  U  = (const float*)d_in[i]; break; // 512*2048
            case 2048:     bb = (const float*)d_in[i]; break;
            case 65536:    Ws = (const float*)d_in[i]; break; // 512*128
            case 128:      bs = (const float*)d_in[i]; break;
            default: break;
        }
    }
    if (!xc || !xw || !W || !U || !bb || !Ws || !bs) {
        xc = (const float*)d_in[0];
        xw = (const float*)d_in[1];
        W  = (const float*)d_in[2];
        U  = (const float*)d_in[3];
        bb = (const float*)d_in[4];
        Ws = (const float*)d_in[5];
        bs = (const float*)d_in[6];
    }
    float* out = (float*)d_out;   // [128, 256] float32

    k_init<<<256, 256>>>();
    k_wsum<<<8, 256>>>(W);
    k_z0<<<dim3(32, 512), 256>>>(xc, xw, W, bb);

    for (int t = 0; t < T_; t++) {
        k_step<<<dim3(16, 8), 256>>>(W, U, Ws, t);
        k_argmax<<<128, 128>>>(bs, out, t);
    }
}